// round 12
// baseline (speedup 1.0000x reference)
#include <cuda_runtime.h>

// POLLU RHS: dy[b,0:20] = S @ flux(b), flux_r = k_r * C[a_r,b] * C[b_r,b]
// R6: 2 columns/thread via float2 row loads (256B/warp/row -> 2-line bursts,
// 2x in-flight DRAM lines per warp), 512-column blocks, stride-20 smem tile
// (== gmem output layout), per-warp coalesced float4 epilogue, single kernel
// node (k via __ldg, no constant memcpy).

constexpr int TPB  = 256;
constexpr int COLS = 2 * TPB;  // 512 columns per block

__device__ __forceinline__ void compute_dy(
    const float* __restrict__ k,
    float c0, float c1, float c2, float c3, float c4, float c5, float c6,
    float c8, float c9, float c10, float c12, float c13, float c15,
    float c16, float c18, float c19,
    float4* __restrict__ s4)   // 5 float4 slots (one smem column)
{
    float r1  = __ldg(&k[0])  * c0;
    float r2  = __ldg(&k[1])  * c1  * c3;
    float r3  = __ldg(&k[2])  * c4  * c1;
    float r4  = __ldg(&k[3])  * c6;
    float r5  = __ldg(&k[4])  * c6;
    float r6  = __ldg(&k[5])  * c6  * c5;
    float r7  = __ldg(&k[6])  * c8;
    float r8  = __ldg(&k[7])  * c8  * c5;
    float r9  = __ldg(&k[8])  * c10 * c1;
    float r10 = __ldg(&k[9])  * c10 * c0;
    float r11 = __ldg(&k[10]) * c12;
    float r12 = __ldg(&k[11]) * c9  * c1;
    float r13 = __ldg(&k[12]) * c13;
    float r14 = __ldg(&k[13]) * c0  * c5;
    float r15 = __ldg(&k[14]) * c2;
    float r16 = __ldg(&k[15]) * c3;
    float r17 = __ldg(&k[16]) * c3;
    float r18 = __ldg(&k[17]) * c15;
    float r19 = __ldg(&k[18]) * c15;
    float r20 = __ldg(&k[19]) * c16 * c5;
    float r21 = __ldg(&k[20]) * c18;
    float r22 = __ldg(&k[21]) * c18;
    float r23 = __ldg(&k[22]) * c0  * c3;
    float r24 = __ldg(&k[23]) * c18 * c0;
    float r25 = __ldg(&k[24]) * c19;

    float dy0  = -r1 - r10 - r14 - r23 - r24 + r2 + r3 + r9 + r11 + r12 + r22 + r25;
    float dy1  = -r2 - r3 - r9 - r12 + r1 + r21;
    float dy2  = -r15 + r1 + r17 + r19 + r22;
    float dy3  = -r2 - r16 - r17 - r23 + r15;
    float dy4  = -r3 + 2.0f * r4 + r6 + r7 + r13 + r20;
    float dy5  = -r6 - r8 - r14 - r20 + r3 + 2.0f * r18;
    float dy6  = -r4 - r5 - r6 + r13;
    float dy7  =  r4 + r5 + r6 + r7;
    float dy8  = -r7 - r8;
    float dy9  = -r12 + r7 + r9;
    float dy10 = -r9 - r10 + r8 + r11;
    float dy11 =  r9;
    float dy12 = -r11 + r10;
    float dy13 = -r13 + r12;
    float dy14 =  r14;
    float dy15 = -r18 - r19 + r16;
    float dy16 = -r20;
    float dy17 =  r20;
    float dy18 = -r21 - r22 - r24 + r23 + r25;
    float dy19 = -r25 + r24;

    s4[0] = make_float4(dy0,  dy1,  dy2,  dy3);
    s4[1] = make_float4(dy4,  dy5,  dy6,  dy7);
    s4[2] = make_float4(dy8,  dy9,  dy10, dy11);
    s4[3] = make_float4(dy12, dy13, dy14, dy15);
    s4[4] = make_float4(dy16, dy17, dy18, dy19);
}

__global__ void __launch_bounds__(TPB) pollu_kernel(
    const float* __restrict__ C,   // [20, B]
    const float* __restrict__ k,   // [25]
    float* __restrict__ out,       // [B, 20]
    int B)
{
    __shared__ float sm[COLS * 20];  // 40960 B; layout == out[base:base+COLS, :]

    const int tid  = threadIdx.x;
    const int wid  = tid >> 5;
    const int lane = tid & 31;
    const int base = blockIdx.x * COLS;
    const int b0   = base + 2 * tid;   // this thread's even column (B is even)

    if (b0 < B) {
        // float2 row loads: 256B per warp per row, fully coalesced, streaming.
        const size_t h = (size_t)(b0 >> 1);   // float2 index within a row
        const size_t Bh = (size_t)B >> 1;
        const float2* C2 = reinterpret_cast<const float2*>(C);
        float2 v0  = __ldcs(&C2[0  * Bh + h]);
        float2 v1  = __ldcs(&C2[1  * Bh + h]);
        float2 v2  = __ldcs(&C2[2  * Bh + h]);
        float2 v3  = __ldcs(&C2[3  * Bh + h]);
        float2 v4  = __ldcs(&C2[4  * Bh + h]);
        float2 v5  = __ldcs(&C2[5  * Bh + h]);
        float2 v6  = __ldcs(&C2[6  * Bh + h]);
        float2 v8  = __ldcs(&C2[8  * Bh + h]);
        float2 v9  = __ldcs(&C2[9  * Bh + h]);
        float2 v10 = __ldcs(&C2[10 * Bh + h]);
        float2 v12 = __ldcs(&C2[12 * Bh + h]);
        float2 v13 = __ldcs(&C2[13 * Bh + h]);
        float2 v15 = __ldcs(&C2[15 * Bh + h]);
        float2 v16 = __ldcs(&C2[16 * Bh + h]);
        float2 v18 = __ldcs(&C2[18 * Bh + h]);
        float2 v19 = __ldcs(&C2[19 * Bh + h]);

        float4* sA = reinterpret_cast<float4*>(&sm[(2 * tid) * 20]);
        compute_dy(k, v0.x, v1.x, v2.x, v3.x, v4.x, v5.x, v6.x, v8.x, v9.x,
                   v10.x, v12.x, v13.x, v15.x, v16.x, v18.x, v19.x, sA);

        float4* sB = reinterpret_cast<float4*>(&sm[(2 * tid + 1) * 20]);
        compute_dy(k, v0.y, v1.y, v2.y, v3.y, v4.y, v5.y, v6.y, v8.y, v9.y,
                   v10.y, v12.y, v13.y, v15.y, v16.y, v18.y, v19.y, sB);
    }
    __syncwarp();

    // Per-warp epilogue: warp w owns 64 cols -> 320 contiguous float4s.
    const long long nf4_total = (long long)B * 5;
    const long long gbase     = (long long)base * 5 + (long long)wid * 320;
    const float4* s4 = reinterpret_cast<const float4*>(sm) + wid * 320;
    float4* o4 = reinterpret_cast<float4*>(out);

    #pragma unroll
    for (int i = 0; i < 10; i++) {
        int f = lane + i * 32;
        long long g = gbase + f;
        if (g < nf4_total) {
            __stcs(&o4[g], s4[f]);
        }
    }
}

extern "C" void kernel_launch(void* const* d_in, const int* in_sizes, int n_in,
                              void* d_out, int out_size) {
    // metadata order: t [1], conc_in [20*B], k [25]
    const float* conc = (const float*)d_in[1];
    const float* k    = (const float*)d_in[2];
    float* out        = (float*)d_out;
    int B = in_sizes[1] / 20;

    int blocks = (B + COLS - 1) / COLS;
    pollu_kernel<<<blocks, TPB>>>(conc, k, out, B);
}

// round 15
// speedup vs baseline: 1.0123x; 1.0123x over previous
#include <cuda_runtime.h>
#include <cstdint>

// POLLU RHS: dy[b,0:20] = S @ flux(b), flux_r = k_r * C[a_r,b] * C[b_r,b]
// R7: compute phase identical to R3 (1 col/thread, 16 coalesced streaming row
// loads, fully unrolled stoichiometry, stride-20 smem tile == gmem output
// layout). Epilogue replaced by a single TMA bulk store per block:
// cp.async.bulk.global.shared::cta moves the whole 20KB tile smem->gmem,
// removing ~1280 STG wavefronts/block from the L1/LSU path so the inbound
// LDG stream runs uncontended.

constexpr int TPB = 256;

__device__ __forceinline__ uint32_t smem_u32(const void* p) {
    uint32_t a;
    asm("{ .reg .u64 t; cvta.to.shared.u64 t, %1; cvt.u32.u64 %0, t; }"
        : "=r"(a) : "l"(p));
    return a;
}

__global__ void __launch_bounds__(TPB) pollu_kernel(
    const float* __restrict__ C,   // [20, B]
    const float* __restrict__ k,   // [25]
    float* __restrict__ out,       // [B, 20]
    int B)
{
    __shared__ __align__(16) float sm[TPB * 20];  // == out[base:base+TPB, 0:20]

    const int tid  = threadIdx.x;
    const int base = blockIdx.x * TPB;
    const int b    = base + tid;

    if (b < B) {
        // Coalesced, streaming (use-once) row loads. Rows 7,11,14,17 unused.
        float c0  = __ldcs(&C[(size_t)0  * B + b]);
        float c1  = __ldcs(&C[(size_t)1  * B + b]);
        float c2  = __ldcs(&C[(size_t)2  * B + b]);
        float c3  = __ldcs(&C[(size_t)3  * B + b]);
        float c4  = __ldcs(&C[(size_t)4  * B + b]);
        float c5  = __ldcs(&C[(size_t)5  * B + b]);
        float c6  = __ldcs(&C[(size_t)6  * B + b]);
        float c8  = __ldcs(&C[(size_t)8  * B + b]);
        float c9  = __ldcs(&C[(size_t)9  * B + b]);
        float c10 = __ldcs(&C[(size_t)10 * B + b]);
        float c12 = __ldcs(&C[(size_t)12 * B + b]);
        float c13 = __ldcs(&C[(size_t)13 * B + b]);
        float c15 = __ldcs(&C[(size_t)15 * B + b]);
        float c16 = __ldcs(&C[(size_t)16 * B + b]);
        float c18 = __ldcs(&C[(size_t)18 * B + b]);
        float c19 = __ldcs(&C[(size_t)19 * B + b]);

        float r1  = __ldg(&k[0])  * c0;
        float r2  = __ldg(&k[1])  * c1  * c3;
        float r3  = __ldg(&k[2])  * c4  * c1;
        float r4  = __ldg(&k[3])  * c6;
        float r5  = __ldg(&k[4])  * c6;
        float r6  = __ldg(&k[5])  * c6  * c5;
        float r7  = __ldg(&k[6])  * c8;
        float r8  = __ldg(&k[7])  * c8  * c5;
        float r9  = __ldg(&k[8])  * c10 * c1;
        float r10 = __ldg(&k[9])  * c10 * c0;
        float r11 = __ldg(&k[10]) * c12;
        float r12 = __ldg(&k[11]) * c9  * c1;
        float r13 = __ldg(&k[12]) * c13;
        float r14 = __ldg(&k[13]) * c0  * c5;
        float r15 = __ldg(&k[14]) * c2;
        float r16 = __ldg(&k[15]) * c3;
        float r17 = __ldg(&k[16]) * c3;
        float r18 = __ldg(&k[17]) * c15;
        float r19 = __ldg(&k[18]) * c15;
        float r20 = __ldg(&k[19]) * c16 * c5;
        float r21 = __ldg(&k[20]) * c18;
        float r22 = __ldg(&k[21]) * c18;
        float r23 = __ldg(&k[22]) * c0  * c3;
        float r24 = __ldg(&k[23]) * c18 * c0;
        float r25 = __ldg(&k[24]) * c19;

        float dy0  = -r1 - r10 - r14 - r23 - r24 + r2 + r3 + r9 + r11 + r12 + r22 + r25;
        float dy1  = -r2 - r3 - r9 - r12 + r1 + r21;
        float dy2  = -r15 + r1 + r17 + r19 + r22;
        float dy3  = -r2 - r16 - r17 - r23 + r15;
        float dy4  = -r3 + 2.0f * r4 + r6 + r7 + r13 + r20;
        float dy5  = -r6 - r8 - r14 - r20 + r3 + 2.0f * r18;
        float dy6  = -r4 - r5 - r6 + r13;
        float dy7  =  r4 + r5 + r6 + r7;
        float dy8  = -r7 - r8;
        float dy9  = -r12 + r7 + r9;
        float dy10 = -r9 - r10 + r8 + r11;
        float dy11 =  r9;
        float dy12 = -r11 + r10;
        float dy13 = -r13 + r12;
        float dy14 =  r14;
        float dy15 = -r18 - r19 + r16;
        float dy16 = -r20;
        float dy17 =  r20;
        float dy18 = -r21 - r22 - r24 + r23 + r25;
        float dy19 = -r25 + r24;

        // Stage to smem at 80B column stride (conflict-free STS.128).
        float4* s4 = reinterpret_cast<float4*>(&sm[tid * 20]);
        s4[0] = make_float4(dy0,  dy1,  dy2,  dy3);
        s4[1] = make_float4(dy4,  dy5,  dy6,  dy7);
        s4[2] = make_float4(dy8,  dy9,  dy10, dy11);
        s4[3] = make_float4(dy12, dy13, dy14, dy15);
        s4[4] = make_float4(dy16, dy17, dy18, dy19);
    }
    __syncthreads();

    // One TMA bulk store per block: smem tile -> contiguous gmem span.
    if (tid == 0) {
        int ncols = B - base;
        if (ncols > TPB) ncols = TPB;
        const uint32_t bytes = (uint32_t)ncols * 80u;   // multiple of 16
        float* gdst = out + (size_t)base * 20;          // 16B-aligned (80B*base)

        asm volatile("fence.proxy.async.shared::cta;" ::: "memory");
        asm volatile(
            "cp.async.bulk.global.shared::cta.bulk_group [%0], [%1], %2;"
            :: "l"(gdst), "r"(smem_u32(sm)), "r"(bytes) : "memory");
        asm volatile("cp.async.bulk.commit_group;" ::: "memory");
        asm volatile("cp.async.bulk.wait_group.read 0;" ::: "memory");
    }
    // Block may not retire while the bulk op still reads smem; thread 0's
    // wait_group.read 0 + this barrier guarantees that.
    __syncthreads();
}

extern "C" void kernel_launch(void* const* d_in, const int* in_sizes, int n_in,
                              void* d_out, int out_size) {
    // metadata order: t [1], conc_in [20*B], k [25]
    const float* conc = (const float*)d_in[1];
    const float* k    = (const float*)d_in[2];
    float* out        = (float*)d_out;
    int B = in_sizes[1] / 20;

    int blocks = (B + TPB - 1) / TPB;
    pollu_kernel<<<blocks, TPB>>>(conc, k, out, B);
}